// round 5
// baseline (speedup 1.0000x reference)
#include <cuda_runtime.h>

#define D 64
#define GMAX 64
#define NMAX 100000
#define EMAX 1250000

// ---- scratch (device globals: no allocation allowed). float4 => 16B alignment. ----
__device__ float4 g_h4[NMAX * D / 4];     // h' = (x @ W) * dis[row]
__device__ float4 g_agg4[NMAX * D / 4];   // scatter accumulator (init = h' -> self loop folded)
__device__ float4 g_buf04[NMAX * D / 4];  // layer ping-pong
__device__ float4 g_buf14[NMAX * D / 4];
__device__ float g_deg[NMAX];
__device__ float g_dis[NMAX];
__device__ float g_cnt[GMAX];
__device__ float g_gmax[GMAX * D];
__device__ float g_gsum[GMAX * D];

#define g_h ((float*)g_h4)
#define g_agg ((float*)g_agg4)

// ---- init: deg=1 (self loop), zero counters / pool buffers / graph output ----
__global__ void k_init(float* __restrict__ out_graph, int n) {
    int i = blockIdx.x * blockDim.x + threadIdx.x;
    if (i < n) g_deg[i] = 1.0f;
    if (i < GMAX) g_cnt[i] = 0.0f;
    if (i < GMAX * D) { g_gmax[i] = 0.0f; g_gsum[i] = 0.0f; }
    if (i < GMAX * 2 * D) out_graph[i] = 0.0f;
}

// ---- degree over destinations ----
__global__ void k_deg(const int* __restrict__ ei, int e) {
    int i = blockIdx.x * blockDim.x + threadIdx.x;
    if (i < e) atomicAdd(&g_deg[ei[e + i]], 1.0f);
}

// ---- dis = rsqrt(deg); per-graph node counts ----
__global__ void k_dis(const int* __restrict__ batch, int n) {
    int i = blockIdx.x * blockDim.x + threadIdx.x;
    if (i < n) {
        g_dis[i] = rsqrtf(g_deg[i]);
        atomicAdd(&g_cnt[batch[i]], 1.0f);
    }
}

// ---- h' = (x @ W) * dis[row]; agg initialized to h' (self-loop term) ----
// 64 rows/block, 256 threads: thread (r, c) computes row r, contiguous cols [16c, 16c+16).
// Inner loop: 1 scalar LDS (broadcast) + 4 LDS.128 per k  (was 17 scalar LDS in R2).
__global__ void k_gemm(const float* __restrict__ x, const float* __restrict__ W, int n) {
    __shared__ float xs[64 * 68];      // stride 68: conflict-free broadcast reads
    __shared__ float4 ws4[64 * 16];    // W row-major as float4
    int t = threadIdx.x;
    int R0 = blockIdx.x * 64;
    int rows = min(64, n - R0);

    for (int i = t; i < 64 * 16; i += 256)
        ws4[i] = ((const float4*)W)[i];
    for (int i = t; i < rows * 16; i += 256) {
        int rr = i >> 4, c4 = i & 15;
        *((float4*)(xs + rr * 68) + c4) = *((const float4*)(x + (size_t)(R0 + rr) * 64) + c4);
    }
    __syncthreads();

    int r = t >> 2;      // 0..63
    int c = t & 3;       // 0..3 -> cols [16c, 16c+16)
    if (r >= rows) return;

    float4 a0 = {0,0,0,0}, a1 = {0,0,0,0}, a2 = {0,0,0,0}, a3 = {0,0,0,0};
#pragma unroll
    for (int k = 0; k < 64; k++) {
        float xv = xs[r * 68 + k];
        const float4* wr = ws4 + k * 16 + c * 4;
        float4 w0 = wr[0], w1 = wr[1], w2 = wr[2], w3 = wr[3];
        a0.x = fmaf(xv, w0.x, a0.x); a0.y = fmaf(xv, w0.y, a0.y);
        a0.z = fmaf(xv, w0.z, a0.z); a0.w = fmaf(xv, w0.w, a0.w);
        a1.x = fmaf(xv, w1.x, a1.x); a1.y = fmaf(xv, w1.y, a1.y);
        a1.z = fmaf(xv, w1.z, a1.z); a1.w = fmaf(xv, w1.w, a1.w);
        a2.x = fmaf(xv, w2.x, a2.x); a2.y = fmaf(xv, w2.y, a2.y);
        a2.z = fmaf(xv, w2.z, a2.z); a2.w = fmaf(xv, w2.w, a2.w);
        a3.x = fmaf(xv, w3.x, a3.x); a3.y = fmaf(xv, w3.y, a3.y);
        a3.z = fmaf(xv, w3.z, a3.z); a3.w = fmaf(xv, w3.w, a3.w);
    }
    int gr = R0 + r;
    float s = g_dis[gr];
    float4* hp = (float4*)(g_h + (size_t)gr * 64) + c * 4;
    float4* ap = (float4*)(g_agg + (size_t)gr * 64) + c * 4;
    float4 o0 = {a0.x*s, a0.y*s, a0.z*s, a0.w*s};
    float4 o1 = {a1.x*s, a1.y*s, a1.z*s, a1.w*s};
    float4 o2 = {a2.x*s, a2.y*s, a2.z*s, a2.w*s};
    float4 o3 = {a3.x*s, a3.y*s, a3.z*s, a3.w*s};
    hp[0] = o0; hp[1] = o1; hp[2] = o2; hp[3] = o3;
    ap[0] = o0; ap[1] = o1; ap[2] = o2; ap[3] = o3;
}

// ---- edge scatter: agg[dst] += h'[src]; 16 threads/edge, float4 gather + 4 atomics ----
// (identical to the R2 kernel that passed at 860us)
__global__ void k_scatter(const int* __restrict__ ei, int e) {
    int idx = blockIdx.x * blockDim.x + threadIdx.x;
    int eid = idx >> 4;
    if (eid >= e) return;
    int chunk = (idx & 15) << 2;             // 0,4,...,60
    int src = ei[eid];
    int dst = ei[e + eid];
    float4 v = *(const float4*)(g_h + (size_t)src * 64 + chunk);
    float* a = g_agg + (size_t)dst * 64 + chunk;
    atomicAdd(a + 0, v.x);
    atomicAdd(a + 1, v.y);
    atomicAdd(a + 2, v.z);
    atomicAdd(a + 3, v.w);
}

// ---- epilogue: x_out = relu(dis*agg + b) + graph max/mean pooling ----
// 128 rows/block, 256 threads: thread = (rr in 0..3, dim j). Block-local smem reduce
// when the whole 128-row stripe belongs to one graph (batch sorted -> common case).
__global__ void k_epilogue(const float* __restrict__ b, const int* __restrict__ batch,
                           float* __restrict__ xout, int n) {
    int t = threadIdx.x;
    int j = t & 63;
    int rr = t >> 6;
    int R0 = blockIdx.x * 128;
    int rows = min(128, n - R0);
    int gfirst = batch[R0];
    int glast = batch[R0 + rows - 1];
    bool uniform = (gfirst == glast);
    float bj = b[j];

    float lsum = 0.0f, lmax = 0.0f;
    for (int k = rr; k < rows; k += 4) {
        int r = R0 + k;
        float v = fmaf(g_dis[r], g_agg[(size_t)r * 64 + j], bj);
        v = fmaxf(v, 0.0f);
        xout[(size_t)r * 64 + j] = v;
        if (uniform) {
            lsum += v;
            lmax = fmaxf(lmax, v);
        } else {
            int g = batch[r];
            atomicAdd(&g_gsum[g * 64 + j], v);
            atomicMax((unsigned int*)&g_gmax[g * 64 + j], __float_as_uint(v));
        }
    }
    if (uniform) {
        __shared__ float ssum[4][64];
        __shared__ float smax[4][64];
        ssum[rr][j] = lsum;
        smax[rr][j] = lmax;
        __syncthreads();
        if (rr == 0) {
            float s = ssum[0][j] + ssum[1][j] + ssum[2][j] + ssum[3][j];
            float m = fmaxf(fmaxf(smax[0][j], smax[1][j]), fmaxf(smax[2][j], smax[3][j]));
            atomicAdd(&g_gsum[gfirst * 64 + j], s);
            atomicMax((unsigned int*)&g_gmax[gfirst * 64 + j], __float_as_uint(m));
        }
    }
}

// ---- accumulate per-layer pooled features into graph output; reset pool buffers ----
__global__ void k_graphacc(float* __restrict__ out_graph) {
    int i = blockIdx.x * blockDim.x + threadIdx.x;
    if (i >= GMAX * 64) return;
    int g = i >> 6, j = i & 63;
    out_graph[g * 128 + j] += g_gmax[i];
    out_graph[g * 128 + 64 + j] += g_gsum[i] / g_cnt[g];
    g_gmax[i] = 0.0f;
    g_gsum[i] = 0.0f;
}

extern "C" void kernel_launch(void* const* d_in, const int* in_sizes, int n_in,
                              void* d_out, int out_size) {
    const float* x = (const float*)d_in[0];
    const int* ei = (const int*)d_in[1];
    const int* batch = (const int*)d_in[2];
    const float* Ws[3] = {(const float*)d_in[3], (const float*)d_in[5], (const float*)d_in[7]};
    const float* bs[3] = {(const float*)d_in[4], (const float*)d_in[6], (const float*)d_in[8]};

    int n = in_sizes[2];
    int e = in_sizes[1] / 2;

    float* out = (float*)d_out;
    float* out_nodes = out;
    float* out_graph = out + (size_t)n * 64;

    float *buf0, *buf1;
    cudaGetSymbolAddress((void**)&buf0, g_buf04);
    cudaGetSymbolAddress((void**)&buf1, g_buf14);

    k_init<<<(n + 255) / 256, 256>>>(out_graph, n);
    k_deg<<<(e + 255) / 256, 256>>>(ei, e);
    k_dis<<<(n + 255) / 256, 256>>>(batch, n);

    const float* xin = x;
    float* xouts[3] = {buf0, buf1, out_nodes};
    int scatter_blocks = (int)(((long long)e * 16 + 255) / 256);
    for (int l = 0; l < 3; l++) {
        k_gemm<<<(n + 63) / 64, 256>>>(xin, Ws[l], n);
        k_scatter<<<scatter_blocks, 256>>>(ei, e);
        k_epilogue<<<(n + 127) / 128, 256>>>(bs[l], batch, xouts[l], n);
        k_graphacc<<<16, 256>>>(out_graph);
        xin = xouts[l];
    }
}

// round 6
// speedup vs baseline: 1.5805x; 1.5805x over previous
#include <cuda_runtime.h>

#define D 64
#define GMAX 64
#define NMAX 100000
#define EMAX 1250000

// ---- scratch (device globals: no allocation allowed). float4 => 16B alignment. ----
__device__ float4 g_h4[NMAX * D / 4];     // h' = (x @ W) * dis[row]
__device__ float4 g_agg4[NMAX * D / 4];   // scatter accumulator (init = h' -> self loop folded)
__device__ float4 g_buf04[NMAX * D / 4];  // layer ping-pong
__device__ float4 g_buf14[NMAX * D / 4];
__device__ float g_deg[NMAX];
__device__ float g_dis[NMAX];
__device__ float g_cnt[GMAX];
__device__ float g_gmax[GMAX * D];
__device__ float g_gsum[GMAX * D];

#define g_h ((float*)g_h4)
#define g_agg ((float*)g_agg4)

// ---- init: deg=1 (self loop), zero counters / pool buffers / graph output ----
__global__ void k_init(float* __restrict__ out_graph, int n) {
    int i = blockIdx.x * blockDim.x + threadIdx.x;
    if (i < n) g_deg[i] = 1.0f;
    if (i < GMAX) g_cnt[i] = 0.0f;
    if (i < GMAX * D) { g_gmax[i] = 0.0f; g_gsum[i] = 0.0f; }
    if (i < GMAX * 2 * D) out_graph[i] = 0.0f;
}

// ---- degree over destinations ----
__global__ void k_deg(const int* __restrict__ ei, int e) {
    int i = blockIdx.x * blockDim.x + threadIdx.x;
    if (i < e) atomicAdd(&g_deg[ei[e + i]], 1.0f);
}

// ---- dis = rsqrt(deg); per-graph node counts ----
__global__ void k_dis(const int* __restrict__ batch, int n) {
    int i = blockIdx.x * blockDim.x + threadIdx.x;
    if (i < n) {
        g_dis[i] = rsqrtf(g_deg[i]);
        atomicAdd(&g_cnt[batch[i]], 1.0f);
    }
}

// ---- h' = (x @ W) * dis[row]; agg initialized to h' (self-loop term) ----
// EXACT R2 version (72us measured; the vectorized variant regressed to 110us).
// 64 rows per block, 256 threads: 4 threads/row, 16 cols each (stride-4 smem reads)
__global__ void k_gemm(const float* __restrict__ x, const float* __restrict__ W, int n) {
    __shared__ float xs[64 * 68];   // stride 68: conflict-free xs[r*68+k] reads
    __shared__ float ws[64 * 64];
    int t = threadIdx.x;
    int R0 = blockIdx.x * 64;
    int rows = min(64, n - R0);

    for (int i = t; i < 64 * 16; i += 256)
        ((float4*)ws)[i] = ((const float4*)W)[i];
    for (int i = t; i < rows * 16; i += 256) {
        int rr = i >> 4, c4 = i & 15;
        *((float4*)(xs + rr * 68) + c4) = *((const float4*)(x + (size_t)(R0 + rr) * 64) + c4);
    }
    __syncthreads();

    int r = t >> 2;      // 0..63
    int c = t & 3;       // 0..3
    if (r >= rows) return;

    float acc[16];
#pragma unroll
    for (int j = 0; j < 16; j++) acc[j] = 0.0f;
#pragma unroll
    for (int k = 0; k < 64; k++) {
        float xv = xs[r * 68 + k];
        const float* wrow = ws + k * 64;
#pragma unroll
        for (int j = 0; j < 16; j++) acc[j] += xv * wrow[4 * j + c];
    }
    int gr = R0 + r;
    float s = g_dis[gr];
    float* hp = g_h + (size_t)gr * 64;
    float* ap = g_agg + (size_t)gr * 64;
#pragma unroll
    for (int j = 0; j < 16; j++) {
        float v = acc[j] * s;
        hp[4 * j + c] = v;
        ap[4 * j + c] = v;
    }
}

// ---- 16B vector atomic via CUDA intrinsic (sm_90+); scalar fallback otherwise ----
__device__ __forceinline__ void agg_add_v4(float4* a, float4 v) {
#if __CUDA_ARCH__ >= 900
    atomicAdd(a, v);
#else
    float* p = (float*)a;
    atomicAdd(p + 0, v.x);
    atomicAdd(p + 1, v.y);
    atomicAdd(p + 2, v.z);
    atomicAdd(p + 3, v.w);
#endif
}

// ---- edge scatter: agg[dst] += h'[src]; 8 threads/edge, 2 x (float4 gather + v4 atomic) ----
__global__ void k_scatter(const int* __restrict__ ei, int e) {
    int idx = blockIdx.x * blockDim.x + threadIdx.x;
    int eid = idx >> 3;
    if (eid >= e) return;
    int c0 = (idx & 7) << 3;                 // 0,8,...,56
    int src = ei[eid];
    int dst = ei[e + eid];
    const float4* hp = (const float4*)(g_h + (size_t)src * 64 + c0);
    float4* ap = (float4*)(g_agg + (size_t)dst * 64 + c0);
    float4 v0 = hp[0];
    float4 v1 = hp[1];
    agg_add_v4(ap, v0);
    agg_add_v4(ap + 1, v1);
}

// ---- epilogue: x_out = relu(dis*agg + b) + graph max/mean pooling ----
// 128 rows/block, 256 threads: thread = (rr in 0..3, dim j). Block-local smem reduce
// when the whole 128-row stripe belongs to one graph (batch sorted -> common case).
__global__ void k_epilogue(const float* __restrict__ b, const int* __restrict__ batch,
                           float* __restrict__ xout, int n) {
    int t = threadIdx.x;
    int j = t & 63;
    int rr = t >> 6;
    int R0 = blockIdx.x * 128;
    int rows = min(128, n - R0);
    int gfirst = batch[R0];
    int glast = batch[R0 + rows - 1];
    bool uniform = (gfirst == glast);
    float bj = b[j];

    float lsum = 0.0f, lmax = 0.0f;
    for (int k = rr; k < rows; k += 4) {
        int r = R0 + k;
        float v = fmaf(g_dis[r], g_agg[(size_t)r * 64 + j], bj);
        v = fmaxf(v, 0.0f);
        xout[(size_t)r * 64 + j] = v;
        if (uniform) {
            lsum += v;
            lmax = fmaxf(lmax, v);
        } else {
            int g = batch[r];
            atomicAdd(&g_gsum[g * 64 + j], v);
            atomicMax((unsigned int*)&g_gmax[g * 64 + j], __float_as_uint(v));
        }
    }
    if (uniform) {
        __shared__ float ssum[4][64];
        __shared__ float smax[4][64];
        ssum[rr][j] = lsum;
        smax[rr][j] = lmax;
        __syncthreads();
        if (rr == 0) {
            float s = ssum[0][j] + ssum[1][j] + ssum[2][j] + ssum[3][j];
            float m = fmaxf(fmaxf(smax[0][j], smax[1][j]), fmaxf(smax[2][j], smax[3][j]));
            atomicAdd(&g_gsum[gfirst * 64 + j], s);
            atomicMax((unsigned int*)&g_gmax[gfirst * 64 + j], __float_as_uint(m));
        }
    }
}

// ---- accumulate per-layer pooled features into graph output; reset pool buffers ----
__global__ void k_graphacc(float* __restrict__ out_graph) {
    int i = blockIdx.x * blockDim.x + threadIdx.x;
    if (i >= GMAX * 64) return;
    int g = i >> 6, j = i & 63;
    out_graph[g * 128 + j] += g_gmax[i];
    out_graph[g * 128 + 64 + j] += g_gsum[i] / g_cnt[g];
    g_gmax[i] = 0.0f;
    g_gsum[i] = 0.0f;
}

extern "C" void kernel_launch(void* const* d_in, const int* in_sizes, int n_in,
                              void* d_out, int out_size) {
    const float* x = (const float*)d_in[0];
    const int* ei = (const int*)d_in[1];
    const int* batch = (const int*)d_in[2];
    const float* Ws[3] = {(const float*)d_in[3], (const float*)d_in[5], (const float*)d_in[7]};
    const float* bs[3] = {(const float*)d_in[4], (const float*)d_in[6], (const float*)d_in[8]};

    int n = in_sizes[2];
    int e = in_sizes[1] / 2;

    float* out = (float*)d_out;
    float* out_nodes = out;
    float* out_graph = out + (size_t)n * 64;

    float *buf0, *buf1;
    cudaGetSymbolAddress((void**)&buf0, g_buf04);
    cudaGetSymbolAddress((void**)&buf1, g_buf14);

    k_init<<<(n + 255) / 256, 256>>>(out_graph, n);
    k_deg<<<(e + 255) / 256, 256>>>(ei, e);
    k_dis<<<(n + 255) / 256, 256>>>(batch, n);

    const float* xin = x;
    float* xouts[3] = {buf0, buf1, out_nodes};
    int scatter_blocks = (int)(((long long)e * 8 + 255) / 256);
    for (int l = 0; l < 3; l++) {
        k_gemm<<<(n + 63) / 64, 256>>>(xin, Ws[l], n);
        k_scatter<<<scatter_blocks, 256>>>(ei, e);
        k_epilogue<<<(n + 127) / 128, 256>>>(bs[l], batch, xouts[l], n);
        k_graphacc<<<16, 256>>>(out_graph);
        xin = xouts[l];
    }
}

// round 7
// speedup vs baseline: 2.2802x; 1.4427x over previous
#include <cuda_runtime.h>

#define D 64
#define GMAX 64
#define NMAX 100000
#define EMAX 1250000

// ---- scratch (device globals). float4 => 16B alignment. ----
__device__ float4 g_h4[NMAX * D / 4];     // h' = (x @ W) * dis[row]
__device__ float4 g_buf04[NMAX * D / 4];  // layer ping-pong
__device__ float4 g_buf14[NMAX * D / 4];
__device__ int   g_degE[NMAX];            // real in-degree (no self loop)
__device__ int   g_start[NMAX];           // CSR exclusive offsets
__device__ int   g_cursor[NMAX];          // fill cursors
__device__ int   g_csr[EMAX];             // src ids grouped by dst
__device__ int   g_bsum[256];             // scan block sums
__device__ int   g_boff[256];             // scan block offsets
__device__ float g_dis[NMAX];
__device__ float g_cnt[GMAX];
__device__ float g_gmax[GMAX * D];
__device__ float g_gsum[GMAX * D];

#define g_h ((float*)g_h4)

// ---- init ----
__global__ void k_init(float* __restrict__ out_graph, int n) {
    int i = blockIdx.x * blockDim.x + threadIdx.x;
    if (i < n) g_degE[i] = 0;
    if (i < GMAX) g_cnt[i] = 0.0f;
    if (i < GMAX * D) { g_gmax[i] = 0.0f; g_gsum[i] = 0.0f; }
    if (i < GMAX * 2 * D) out_graph[i] = 0.0f;
}

// ---- in-degree over destinations (int) ----
__global__ void k_deg(const int* __restrict__ ei, int e) {
    int i = blockIdx.x * blockDim.x + threadIdx.x;
    if (i < e) atomicAdd(&g_degE[ei[e + i]], 1);
}

// ---- dis = rsqrt(degE + 1); per-graph node counts ----
__global__ void k_dis(const int* __restrict__ batch, int n) {
    int i = blockIdx.x * blockDim.x + threadIdx.x;
    if (i < n) {
        g_dis[i] = rsqrtf((float)(g_degE[i] + 1));
        atomicAdd(&g_cnt[batch[i]], 1.0f);
    }
}

// ---- deterministic 2-level exclusive scan of g_degE -> g_start ----
__global__ void k_scan1(int n) {
    __shared__ int s[512];
    int i = blockIdx.x * 512 + threadIdx.x;
    int v = (i < n) ? g_degE[i] : 0;
    s[threadIdx.x] = v;
    __syncthreads();
    for (int off = 1; off < 512; off <<= 1) {
        int t = (threadIdx.x >= off) ? s[threadIdx.x - off] : 0;
        __syncthreads();
        s[threadIdx.x] += t;
        __syncthreads();
    }
    if (i < n) g_start[i] = s[threadIdx.x] - v;   // exclusive
    if (threadIdx.x == 511) g_bsum[blockIdx.x] = s[511];
}
__global__ void k_scan2(int nb) {
    __shared__ int s[256];
    int v = (threadIdx.x < nb) ? g_bsum[threadIdx.x] : 0;
    s[threadIdx.x] = v;
    __syncthreads();
    for (int off = 1; off < 256; off <<= 1) {
        int t = (threadIdx.x >= off) ? s[threadIdx.x - off] : 0;
        __syncthreads();
        s[threadIdx.x] += t;
        __syncthreads();
    }
    if (threadIdx.x < nb) g_boff[threadIdx.x] = s[threadIdx.x] - v;
}
__global__ void k_scan3(int n) {
    int i = blockIdx.x * blockDim.x + threadIdx.x;
    if (i < n) {
        int st = g_start[i] + g_boff[i >> 9];
        g_start[i] = st;
        g_cursor[i] = st;
    }
}

// ---- CSR fill: group src by dst (order within node nondeterministic; sum-safe) ----
__global__ void k_fill(const int* __restrict__ ei, int e) {
    int i = blockIdx.x * blockDim.x + threadIdx.x;
    if (i >= e) return;
    int dst = ei[e + i];
    int pos = atomicAdd(&g_cursor[dst], 1);
    g_csr[pos] = ei[i];
}

// ---- h' = (x @ W) * dis[row] (R2-proven layout; writes only h now) ----
__global__ void k_gemm(const float* __restrict__ x, const float* __restrict__ W, int n) {
    __shared__ float xs[64 * 68];
    __shared__ float ws[64 * 64];
    int t = threadIdx.x;
    int R0 = blockIdx.x * 64;
    int rows = min(64, n - R0);

    for (int i = t; i < 64 * 16; i += 256)
        ((float4*)ws)[i] = ((const float4*)W)[i];
    for (int i = t; i < rows * 16; i += 256) {
        int rr = i >> 4, c4 = i & 15;
        *((float4*)(xs + rr * 68) + c4) = *((const float4*)(x + (size_t)(R0 + rr) * 64) + c4);
    }
    __syncthreads();

    int r = t >> 2;
    int c = t & 3;
    if (r >= rows) return;

    float acc[16];
#pragma unroll
    for (int j = 0; j < 16; j++) acc[j] = 0.0f;
#pragma unroll
    for (int k = 0; k < 64; k++) {
        float xv = xs[r * 68 + k];
        const float* wrow = ws + k * 64;
#pragma unroll
        for (int j = 0; j < 16; j++) acc[j] += xv * wrow[4 * j + c];
    }
    int gr = R0 + r;
    float s = g_dis[gr];
    float* hp = g_h + (size_t)gr * 64;
#pragma unroll
    for (int j = 0; j < 16; j++) hp[4 * j + c] = acc[j] * s;
}

// ---- fused gather + epilogue + pooling ----
// 16 nodes/block x 16 threads/node (one float4 lane each).
// acc = h[node] (self loop) + sum over CSR edges of h[src]; then relu(dis*acc+b),
// write xout, block pooling with uniform fast path.
__global__ void k_gather(const float* __restrict__ b, const int* __restrict__ batch,
                         float* __restrict__ xout, int n) {
    int t = threadIdx.x;
    int ln = t & 15;          // float4 lane (cols 4*ln .. 4*ln+3)
    int nr = t >> 4;          // node-in-block 0..15
    int node = blockIdx.x * 16 + nr;

    float4 acc = {0.f, 0.f, 0.f, 0.f};
    float4 out = {0.f, 0.f, 0.f, 0.f};
    if (node < n) {
        acc = g_h4[(size_t)node * 16 + ln];           // self loop (already *dis[node])
        int st = g_start[node];
        int end = st + g_degE[node];
        int k = st;
        for (; k + 1 < end; k += 2) {
            int s0 = g_csr[k], s1 = g_csr[k + 1];
            float4 v0 = g_h4[(size_t)s0 * 16 + ln];
            float4 v1 = g_h4[(size_t)s1 * 16 + ln];
            acc.x += v0.x + v1.x;
            acc.y += v0.y + v1.y;
            acc.z += v0.z + v1.z;
            acc.w += v0.w + v1.w;
        }
        if (k < end) {
            int s0 = g_csr[k];
            float4 v0 = g_h4[(size_t)s0 * 16 + ln];
            acc.x += v0.x; acc.y += v0.y; acc.z += v0.z; acc.w += v0.w;
        }
        float d = g_dis[node];
        float4 bb = ((const float4*)b)[ln];
        out.x = fmaxf(fmaf(d, acc.x, bb.x), 0.f);
        out.y = fmaxf(fmaf(d, acc.y, bb.y), 0.f);
        out.z = fmaxf(fmaf(d, acc.z, bb.z), 0.f);
        out.w = fmaxf(fmaf(d, acc.w, bb.w), 0.f);
        ((float4*)xout)[(size_t)node * 16 + ln] = out;
    }

    // pooling
    int R0 = blockIdx.x * 16;
    int last = min(R0 + 15, n - 1);
    int gfirst = batch[R0];
    int glast = batch[last];

    if (gfirst == glast) {
        __shared__ float4 ssum[16][16];
        __shared__ float4 smax[16][16];
        ssum[nr][ln] = out;               // out==0 for node>=n: identity for sum, safe for relu-max
        smax[nr][ln] = out;
        __syncthreads();
#pragma unroll
        for (int off = 8; off > 0; off >>= 1) {
            if (nr < off) {
                float4 a = ssum[nr][ln], c2 = ssum[nr + off][ln];
                a.x += c2.x; a.y += c2.y; a.z += c2.z; a.w += c2.w;
                ssum[nr][ln] = a;
                float4 m = smax[nr][ln], c3 = smax[nr + off][ln];
                m.x = fmaxf(m.x, c3.x); m.y = fmaxf(m.y, c3.y);
                m.z = fmaxf(m.z, c3.z); m.w = fmaxf(m.w, c3.w);
                smax[nr][ln] = m;
            }
            __syncthreads();
        }
        if (nr == 0) {
            float4 s = ssum[0][ln];
            float4 m = smax[0][ln];
            float* gs = &g_gsum[gfirst * 64 + ln * 4];
            unsigned int* gm = (unsigned int*)&g_gmax[gfirst * 64 + ln * 4];
            atomicAdd(gs + 0, s.x); atomicAdd(gs + 1, s.y);
            atomicAdd(gs + 2, s.z); atomicAdd(gs + 3, s.w);
            atomicMax(gm + 0, __float_as_uint(m.x));
            atomicMax(gm + 1, __float_as_uint(m.y));
            atomicMax(gm + 2, __float_as_uint(m.z));
            atomicMax(gm + 3, __float_as_uint(m.w));
        }
    } else if (node < n) {
        int g = batch[node];
        float* gs = &g_gsum[g * 64 + ln * 4];
        unsigned int* gm = (unsigned int*)&g_gmax[g * 64 + ln * 4];
        atomicAdd(gs + 0, out.x); atomicAdd(gs + 1, out.y);
        atomicAdd(gs + 2, out.z); atomicAdd(gs + 3, out.w);
        atomicMax(gm + 0, __float_as_uint(out.x));
        atomicMax(gm + 1, __float_as_uint(out.y));
        atomicMax(gm + 2, __float_as_uint(out.z));
        atomicMax(gm + 3, __float_as_uint(out.w));
    }
}

// ---- accumulate per-layer pooled features into graph output; reset pool buffers ----
__global__ void k_graphacc(float* __restrict__ out_graph) {
    int i = blockIdx.x * blockDim.x + threadIdx.x;
    if (i >= GMAX * 64) return;
    int g = i >> 6, j = i & 63;
    out_graph[g * 128 + j] += g_gmax[i];
    out_graph[g * 128 + 64 + j] += g_gsum[i] / g_cnt[g];
    g_gmax[i] = 0.0f;
    g_gsum[i] = 0.0f;
}

extern "C" void kernel_launch(void* const* d_in, const int* in_sizes, int n_in,
                              void* d_out, int out_size) {
    const float* x = (const float*)d_in[0];
    const int* ei = (const int*)d_in[1];
    const int* batch = (const int*)d_in[2];
    const float* Ws[3] = {(const float*)d_in[3], (const float*)d_in[5], (const float*)d_in[7]};
    const float* bs[3] = {(const float*)d_in[4], (const float*)d_in[6], (const float*)d_in[8]};

    int n = in_sizes[2];
    int e = in_sizes[1] / 2;

    float* out = (float*)d_out;
    float* out_nodes = out;
    float* out_graph = out + (size_t)n * 64;

    float *buf0, *buf1;
    cudaGetSymbolAddress((void**)&buf0, g_buf04);
    cudaGetSymbolAddress((void**)&buf1, g_buf14);

    int nb = (n + 511) / 512;   // scan blocks (<=256)

    k_init<<<(n + 255) / 256, 256>>>(out_graph, n);
    k_deg<<<(e + 255) / 256, 256>>>(ei, e);
    k_dis<<<(n + 255) / 256, 256>>>(batch, n);
    k_scan1<<<nb, 512>>>(n);
    k_scan2<<<1, 256>>>(nb);
    k_scan3<<<(n + 255) / 256, 256>>>(n);
    k_fill<<<(e + 255) / 256, 256>>>(ei, e);

    const float* xin = x;
    float* xouts[3] = {buf0, buf1, out_nodes};
    for (int l = 0; l < 3; l++) {
        k_gemm<<<(n + 63) / 64, 256>>>(xin, Ws[l], n);
        k_gather<<<(n + 15) / 16, 256>>>(bs[l], batch, xouts[l], n);
        k_graphacc<<<16, 256>>>(out_graph);
        xin = xouts[l];
    }
}

// round 10
// speedup vs baseline: 2.6506x; 1.1624x over previous
#include <cuda_runtime.h>

#define D 64
#define GMAX 64
#define NMAX 100000
#define EMAX 1250000

// ---- scratch (device globals). float4 => 16B alignment. ----
__device__ float4 g_h4[NMAX * D / 4];     // h' = (x @ W) * dis[row]
__device__ float4 g_buf04[NMAX * D / 4];  // layer ping-pong
__device__ float4 g_buf14[NMAX * D / 4];
__device__ int   g_degE[NMAX];            // real in-degree (no self loop)
__device__ int   g_start[NMAX];           // CSR exclusive offsets
__device__ int   g_cursor[NMAX];          // fill cursors
__device__ int   g_csr[EMAX];             // src ids grouped by dst
__device__ int   g_bsum[256];             // scan block sums
__device__ int   g_boff[256];             // scan block offsets
__device__ float g_dis[NMAX];
__device__ float g_cnt[GMAX];
__device__ float g_gmax[GMAX * D];
__device__ float g_gsum[GMAX * D];

#define g_h ((float*)g_h4)

// ---- init ----
__global__ void k_init(float* __restrict__ out_graph, int n) {
    int i = blockIdx.x * blockDim.x + threadIdx.x;
    if (i < n) g_degE[i] = 0;
    if (i < GMAX) g_cnt[i] = 0.0f;
    if (i < GMAX * D) { g_gmax[i] = 0.0f; g_gsum[i] = 0.0f; }
    if (i < GMAX * 2 * D) out_graph[i] = 0.0f;
}

// ---- in-degree over destinations (int) ----
__global__ void k_deg(const int* __restrict__ ei, int e) {
    int i = blockIdx.x * blockDim.x + threadIdx.x;
    if (i < e) atomicAdd(&g_degE[ei[e + i]], 1);
}

// ---- dis = rsqrt(degE + 1); per-graph node counts ----
__global__ void k_dis(const int* __restrict__ batch, int n) {
    int i = blockIdx.x * blockDim.x + threadIdx.x;
    if (i < n) {
        g_dis[i] = rsqrtf((float)(g_degE[i] + 1));
        atomicAdd(&g_cnt[batch[i]], 1.0f);
    }
}

// ---- deterministic 2-level exclusive scan of g_degE -> g_start ----
__global__ void k_scan1(int n) {
    __shared__ int s[512];
    int i = blockIdx.x * 512 + threadIdx.x;
    int v = (i < n) ? g_degE[i] : 0;
    s[threadIdx.x] = v;
    __syncthreads();
    for (int off = 1; off < 512; off <<= 1) {
        int t = (threadIdx.x >= off) ? s[threadIdx.x - off] : 0;
        __syncthreads();
        s[threadIdx.x] += t;
        __syncthreads();
    }
    if (i < n) g_start[i] = s[threadIdx.x] - v;   // exclusive
    if (threadIdx.x == 511) g_bsum[blockIdx.x] = s[511];
}
__global__ void k_scan2(int nb) {
    __shared__ int s[256];
    int v = (threadIdx.x < nb) ? g_bsum[threadIdx.x] : 0;
    s[threadIdx.x] = v;
    __syncthreads();
    for (int off = 1; off < 256; off <<= 1) {
        int t = (threadIdx.x >= off) ? s[threadIdx.x - off] : 0;
        __syncthreads();
        s[threadIdx.x] += t;
        __syncthreads();
    }
    if (threadIdx.x < nb) g_boff[threadIdx.x] = s[threadIdx.x] - v;
}
__global__ void k_scan3(int n) {
    int i = blockIdx.x * blockDim.x + threadIdx.x;
    if (i < n) {
        int st = g_start[i] + g_boff[i >> 9];
        g_start[i] = st;
        g_cursor[i] = st;
    }
}

// ---- CSR fill: group src by dst (order within node nondeterministic; sum-safe) ----
__global__ void k_fill(const int* __restrict__ ei, int e) {
    int i = blockIdx.x * blockDim.x + threadIdx.x;
    if (i >= e) return;
    int dst = ei[e + i];
    int pos = atomicAdd(&g_cursor[dst], 1);
    g_csr[pos] = ei[i];
}

// ---- h' = (x @ W) * dis[row] ----
// 128 rows/block, 256 threads. Thread (r, c) computes rows r and r+64, cols {4j+c}.
// Per k: 2 xs LDS + 16 ws LDS reused across BOTH rows -> 32 FMA (LDS/FMA 0.56 vs 1.06).
// xs is unpadded (fits 48KB) but each row rotated by (4*row)&63 floats: warp's 8
// distinct r values hit banks (k+4r)%32 = 8 distinct banks -> conflict-free, and
// rows r / r+64 share the same rotation so one offset feeds both loads.
__global__ void k_gemm(const float* __restrict__ x, const float* __restrict__ W, int n) {
    __shared__ float xs[128 * 64];   // 32KB, rotated rows
    __shared__ float ws[64 * 64];    // 16KB -> total 48KB = limit
    int t = threadIdx.x;
    int R0 = blockIdx.x * 128;
    int rows = min(128, n - R0);

    for (int i = t; i < 64 * 16; i += 256)
        ((float4*)ws)[i] = ((const float4*)W)[i];
    for (int i = t; i < rows * 16; i += 256) {
        int rr = i >> 4, c4 = i & 15;
        int roff = ((c4 * 4 + rr * 4) & 63);          // rotated, 16B-aligned
        *(float4*)(xs + rr * 64 + roff) = *((const float4*)(x + (size_t)(R0 + rr) * 64) + c4);
    }
    __syncthreads();

    int r = t >> 2;      // 0..63 -> rows r and r+64
    int c = t & 3;       // 0..3  -> cols 4j+c
    bool v0 = (r < rows);
    bool v1 = (r + 64 < rows);
    if (!v0) return;

    const float* xrow0 = xs + r * 64;
    const float* xrow1 = xs + (r + 64) * 64;
    int rot = (r * 4) & 63;                           // same for r and r+64

    float acc0[16], acc1[16];
#pragma unroll
    for (int j = 0; j < 16; j++) { acc0[j] = 0.0f; acc1[j] = 0.0f; }
#pragma unroll
    for (int k = 0; k < 64; k++) {
        int koff = (k + rot) & 63;
        float xv0 = xrow0[koff];
        float xv1 = xrow1[koff];
        const float* wrow = ws + k * 64;
#pragma unroll
        for (int j = 0; j < 16; j++) {
            float w = wrow[4 * j + c];
            acc0[j] += xv0 * w;
            acc1[j] += xv1 * w;
        }
    }
    int gr0 = R0 + r;
    float s0 = g_dis[gr0];
    float* hp0 = g_h + (size_t)gr0 * 64;
#pragma unroll
    for (int j = 0; j < 16; j++) hp0[4 * j + c] = acc0[j] * s0;
    if (v1) {
        int gr1 = gr0 + 64;
        float s1 = g_dis[gr1];
        float* hp1 = g_h + (size_t)gr1 * 64;
#pragma unroll
        for (int j = 0; j < 16; j++) hp1[4 * j + c] = acc1[j] * s1;
    }
}

// ---- fused gather + epilogue + pooling ----
// 16 nodes/block x 16 threads/node (one float4 lane each).
__global__ void k_gather(const float* __restrict__ b, const int* __restrict__ batch,
                         float* __restrict__ xout, int n) {
    int t = threadIdx.x;
    int ln = t & 15;          // float4 lane (cols 4*ln .. 4*ln+3)
    int nr = t >> 4;          // node-in-block 0..15
    int node = blockIdx.x * 16 + nr;

    float4 acc = {0.f, 0.f, 0.f, 0.f};
    float4 out = {0.f, 0.f, 0.f, 0.f};
    if (node < n) {
        acc = g_h4[(size_t)node * 16 + ln];           // self loop (already *dis[node])
        int st = g_start[node];
        int end = st + g_degE[node];
        int k = st;
        for (; k + 1 < end; k += 2) {
            int s0 = g_csr[k], s1 = g_csr[k + 1];
            float4 v0 = g_h4[(size_t)s0 * 16 + ln];
            float4 v1 = g_h4[(size_t)s1 * 16 + ln];
            acc.x += v0.x + v1.x;
            acc.y += v0.y + v1.y;
            acc.z += v0.z + v1.z;
            acc.w += v0.w + v1.w;
        }
        if (k < end) {
            int s0 = g_csr[k];
            float4 v0 = g_h4[(size_t)s0 * 16 + ln];
            acc.x += v0.x; acc.y += v0.y; acc.z += v0.z; acc.w += v0.w;
        }
        float d = g_dis[node];
        float4 bb = ((const float4*)b)[ln];
        out.x = fmaxf(fmaf(d, acc.x, bb.x), 0.f);
        out.y = fmaxf(fmaf(d, acc.y, bb.y), 0.f);
        out.z = fmaxf(fmaf(d, acc.z, bb.z), 0.f);
        out.w = fmaxf(fmaf(d, acc.w, bb.w), 0.f);
        ((float4*)xout)[(size_t)node * 16 + ln] = out;
    }

    // pooling
    int R0 = blockIdx.x * 16;
    int last = min(R0 + 15, n - 1);
    int gfirst = batch[R0];
    int glast = batch[last];

    if (gfirst == glast) {
        __shared__ float4 ssum[16][16];
        __shared__ float4 smax[16][16];
        ssum[nr][ln] = out;               // out==0 for node>=n: identity for sum, safe for relu-max
        smax[nr][ln] = out;
        __syncthreads();
#pragma unroll
        for (int off = 8; off > 0; off >>= 1) {
            if (nr < off) {
                float4 a = ssum[nr][ln], c2 = ssum[nr + off][ln];
                a.x += c2.x; a.y += c2.y; a.z += c2.z; a.w += c2.w;
                ssum[nr][ln] = a;
                float4 m = smax[nr][ln], c3 = smax[nr + off][ln];
                m.x = fmaxf(m.x, c3.x); m.y = fmaxf(m.y, c3.y);
                m.z = fmaxf(m.z, c3.z); m.w = fmaxf(m.w, c3.w);
                smax[nr][ln] = m;
            }
            __syncthreads();
        }
        if (nr == 0) {
            float4 s = ssum[0][ln];
            float4 m = smax[0][ln];
            float* gs = &g_gsum[gfirst * 64 + ln * 4];
            unsigned int* gm = (unsigned int*)&g_gmax[gfirst * 64 + ln * 4];
            atomicAdd(gs + 0, s.x); atomicAdd(gs + 1, s.y);
            atomicAdd(gs + 2, s.z); atomicAdd(gs + 3, s.w);
            atomicMax(gm + 0, __float_as_uint(m.x));
            atomicMax(gm + 1, __float_as_uint(m.y));
            atomicMax(gm + 2, __float_as_uint(m.z));
            atomicMax(gm + 3, __float_as_uint(m.w));
        }
    } else if (node < n) {
        int g = batch[node];
        float* gs = &g_gsum[g * 64 + ln * 4];
        unsigned int* gm = (unsigned int*)&g_gmax[g * 64 + ln * 4];
        atomicAdd(gs + 0, out.x); atomicAdd(gs + 1, out.y);
        atomicAdd(gs + 2, out.z); atomicAdd(gs + 3, out.w);
        atomicMax(gm + 0, __float_as_uint(out.x));
        atomicMax(gm + 1, __float_as_uint(out.y));
        atomicMax(gm + 2, __float_as_uint(out.z));
        atomicMax(gm + 3, __float_as_uint(out.w));
    }
}

// ---- accumulate per-layer pooled features into graph output; reset pool buffers ----
__global__ void k_graphacc(float* __restrict__ out_graph) {
    int i = blockIdx.x * blockDim.x + threadIdx.x;
    if (i >= GMAX * 64) return;
    int g = i >> 6, j = i & 63;
    out_graph[g * 128 + j] += g_gmax[i];
    out_graph[g * 128 + 64 + j] += g_gsum[i] / g_cnt[g];
    g_gmax[i] = 0.0f;
    g_gsum[i] = 0.0f;
}

extern "C" void kernel_launch(void* const* d_in, const int* in_sizes, int n_in,
                              void* d_out, int out_size) {
    const float* x = (const float*)d_in[0];
    const int* ei = (const int*)d_in[1];
    const int* batch = (const int*)d_in[2];
    const float* Ws[3] = {(const float*)d_in[3], (const float*)d_in[5], (const float*)d_in[7]};
    const float* bs[3] = {(const float*)d_in[4], (const float*)d_in[6], (const float*)d_in[8]};

    int n = in_sizes[2];
    int e = in_sizes[1] / 2;

    float* out = (float*)d_out;
    float* out_nodes = out;
    float* out_graph = out + (size_t)n * 64;

    float *buf0, *buf1;
    cudaGetSymbolAddress((void**)&buf0, g_buf04);
    cudaGetSymbolAddress((void**)&buf1, g_buf14);

    int nb = (n + 511) / 512;   // scan blocks (<=256)

    k_init<<<(n + 255) / 256, 256>>>(out_graph, n);
    k_deg<<<(e + 255) / 256, 256>>>(ei, e);
    k_dis<<<(n + 255) / 256, 256>>>(batch, n);
    k_scan1<<<nb, 512>>>(n);
    k_scan2<<<1, 256>>>(nb);
    k_scan3<<<(n + 255) / 256, 256>>>(n);
    k_fill<<<(e + 255) / 256, 256>>>(ei, e);

    const float* xin = x;
    float* xouts[3] = {buf0, buf1, out_nodes};
    for (int l = 0; l < 3; l++) {
        k_gemm<<<(n + 127) / 128, 256>>>(xin, Ws[l], n);
        k_gather<<<(n + 15) / 16, 256>>>(bs[l], batch, xouts[l], n);
        k_graphacc<<<16, 256>>>(out_graph);
        xin = xouts[l];
    }
}